// round 14
// baseline (speedup 1.0000x reference)
#include <cuda_runtime.h>
#include <math.h>
#include <float.h>

#define B_   128
#define H_   512
#define E_   256
#define ND_  128
#define V_   5000
#define K0_  384      // E_ + ND_

typedef unsigned long long u64;

// ---------------- persistent device state ----------------
__device__ __align__(16) float g_h0T[2][H_ * B_];   // [k][b], ping-pong
__device__ __align__(16) float g_h1T[2][H_ * B_];
__device__ __align__(16) float g_c0[H_ * B_];       // cell state [j][b]
__device__ __align__(16) float g_c1[H_ * B_];
__device__ __align__(16) float g_xnT[ND_ * B_];     // noise transposed [k][b] (static)
__device__ __align__(16) float g_cval[125 * B_];    // [p][b]
__device__ int   g_cidx[125 * B_];

__device__ __forceinline__ float sigmf(float x) { return 1.0f / (1.0f + expf(-x)); }

__device__ __forceinline__ u64 pack2(float lo, float hi) {
    u64 r; asm("mov.b64 %0,{%1,%2};" : "=l"(r) : "f"(lo), "f"(hi)); return r;
}
__device__ __forceinline__ void fma2(u64& d, u64 x, u64 w) {
    asm("fma.rn.f32x2 %0,%1,%2,%0;" : "+l"(d) : "l"(x), "l"(w));
}
__device__ __forceinline__ u64 add2(u64 a, u64 b) {
    u64 r; asm("add.rn.f32x2 %0,%1,%2;" : "=l"(r) : "l"(a), "l"(b)); return r;
}
__device__ __forceinline__ void unpack2(u64 a, float& x, float& y) {
    asm("mov.b64 {%0,%1},%2;" : "=f"(x), "=f"(y) : "l"(a));
}
__device__ __forceinline__ float hsum2(u64 a) {
    float x, y; unpack2(a, x, y); return x + y;
}

// ================= init =================
__global__ void k_init(const float* __restrict__ noise) {
    int i = blockIdx.x * 256 + threadIdx.x;
    if (i < H_ * B_) {
        g_h0T[0][i] = 0.f; g_h1T[0][i] = 0.f;
        g_c0[i] = 0.f;     g_c1[i] = 0.f;
    }
    if (i < ND_ * B_) {
        int k = i >> 7, b = i & 127;
        g_xnT[k * B_ + b] = noise[b * ND_ + k];
    }
}

// ================= LSTM kernels =================
// grid 128, block 512 = 16 warps: bg = wid&1 (batch half), rw = (wid>>1)&1 (j pair),
// kz = wid>>2 (4-way K split). Warp tile: 8 rows (4 gates x 2 j) x 64 batch; lane owns 2 b.
// K-paired accumulators: acc[r*2+bl] u64 = (sum even k, sum odd k) for row r, batch b2+bl.
// Weight FFMA2 operand = natural (w_k, w_k+1) pair from LDG.128 -> no dup MOVs.
template<int LAYER>
__global__ void __launch_bounds__(512) k_lstm(
    const float* __restrict__ emb,
    const float* __restrict__ Wih, const float* __restrict__ Whh,
    const float* __restrict__ bih, const float* __restrict__ bhh, int t)
{
    constexpr int KIH = (LAYER == 0) ? K0_ : H_;
    constexpr int SL1 = KIH / 4;              // per-kz seg1 length (96 or 128)
    __shared__ __align__(16) u64 sred[8][32][16];   // 32KB
    __shared__ int s_tok[B_];

    const int tid = threadIdx.x, bid = blockIdx.x;
    const int lane = tid & 31, wid = tid >> 5;
    const int bg = wid & 1, rw = (wid >> 1) & 1, kz = wid >> 2;
    const int grp = wid & 3;                  // rw*2+bg
    const int b2 = bg * 64 + lane * 2;
    const int jbase = bid * 4 + rw * 2;

    // ---- fused token reduce (layer 0) ----
    if (LAYER == 0) {
        if (tid < B_) {
            int tok = 1;
            if (t > 0) {
                float bv = -FLT_MAX; int bi = 0x7fffffff;
                #pragma unroll 5
                for (int p = 0; p < 125; p++) {
                    float v = g_cval[p * B_ + tid];
                    int  ix = g_cidx[p * B_ + tid];
                    if (v > bv || (v == bv && ix < bi)) { bv = v; bi = ix; }
                }
                tok = bi;
            }
            s_tok[tid] = tok;
        }
        __syncthreads();
    }

    const float* hrd = (LAYER == 0) ? g_h0T[t & 1] : g_h1T[t & 1];
    const float* xin = g_h0T[(t + 1) & 1];    // LAYER==1 input
    float*       hwr = (LAYER == 0) ? g_h0T[(t + 1) & 1] : g_h1T[(t + 1) & 1];
    float*       cst = (LAYER == 0) ? g_c0 : g_c1;

    u64 acc[16];
    #pragma unroll
    for (int a = 0; a < 16; a++) acc[a] = 0ull;

    // FMA body for one 4k group: xa0/xa1 = (k0,k1),(k2,k3) pairs for b2; xb* for b2+1.
#define FMA_KP(WB, STRIDE, KK)                                              \
    _Pragma("unroll")                                                       \
    for (int g = 0; g < 4; g++) {                                           \
        _Pragma("unroll")                                                   \
        for (int jj = 0; jj < 2; jj++) {                                    \
            int r = g * 2 + jj;                                             \
            ulonglong2 w = *(const ulonglong2*)((WB) + (size_t)(g * H_ + jbase + jj) * (STRIDE) + (KK)); \
            fma2(acc[r*2+0], xa0, w.x); fma2(acc[r*2+0], xa1, w.y);         \
            fma2(acc[r*2+1], xb0, w.x); fma2(acc[r*2+1], xb1, w.y);         \
        }                                                                   \
    }

    // ---- segment 1: x input ----
    if (LAYER == 0) {
        const float* e0 = emb + (size_t)s_tok[b2]     * E_;
        const float* e1 = emb + (size_t)s_tok[b2 + 1] * E_;
        const int k0 = kz * SL1;
        #pragma unroll 4
        for (int ko = 0; ko < SL1; ko += 4) {
            const int k = k0 + ko;
            u64 xa0, xa1, xb0, xb1;
            if (k < E_) {
                float4 f0 = *(const float4*)(e0 + k);
                float4 f1 = *(const float4*)(e1 + k);
                xa0 = pack2(f0.x, f0.y); xa1 = pack2(f0.z, f0.w);
                xb0 = pack2(f1.x, f1.y); xb1 = pack2(f1.z, f1.w);
            } else {
                const float* nb = g_xnT + (size_t)(k - E_) * B_ + b2;
                float2 a0 = *(const float2*)(nb);
                float2 a1 = *(const float2*)(nb + B_);
                float2 a2 = *(const float2*)(nb + 2 * B_);
                float2 a3 = *(const float2*)(nb + 3 * B_);
                xa0 = pack2(a0.x, a1.x); xa1 = pack2(a2.x, a3.x);
                xb0 = pack2(a0.y, a1.y); xb1 = pack2(a2.y, a3.y);
            }
            FMA_KP(Wih, K0_, k);
        }
    } else {
        const int k0 = kz * SL1;
        #pragma unroll 4
        for (int k = k0; k < k0 + SL1; k += 4) {
            const float* nb = xin + (size_t)k * B_ + b2;
            float2 a0 = *(const float2*)(nb);
            float2 a1 = *(const float2*)(nb + B_);
            float2 a2 = *(const float2*)(nb + 2 * B_);
            float2 a3 = *(const float2*)(nb + 3 * B_);
            u64 xa0 = pack2(a0.x, a1.x), xa1 = pack2(a2.x, a3.x);
            u64 xb0 = pack2(a0.y, a1.y), xb1 = pack2(a2.y, a3.y);
            FMA_KP(Wih, H_, k);
        }
    }

    // ---- segment 2: recurrent ----
    {
        const int k0 = kz * (H_ / 4);
        #pragma unroll 4
        for (int k = k0; k < k0 + H_ / 4; k += 4) {
            const float* nb = hrd + (size_t)k * B_ + b2;
            float2 a0 = *(const float2*)(nb);
            float2 a1 = *(const float2*)(nb + B_);
            float2 a2 = *(const float2*)(nb + 2 * B_);
            float2 a3 = *(const float2*)(nb + 3 * B_);
            u64 xa0 = pack2(a0.x, a1.x), xa1 = pack2(a2.x, a3.x);
            u64 xb0 = pack2(a0.y, a1.y), xb1 = pack2(a2.y, a3.y);
            FMA_KP(Whh, H_, k);
        }
    }
#undef FMA_KP

    // ---- cross-kz reduction: 4 -> 2 -> 1 ----
    if (kz >= 2) {
        #pragma unroll
        for (int a = 0; a < 16; a++) sred[(kz - 2) * 4 + grp][lane][a] = acc[a];
    }
    __syncthreads();
    if (kz < 2) {
        #pragma unroll
        for (int a = 0; a < 16; a++) acc[a] = add2(acc[a], sred[kz * 4 + grp][lane][a]);
    }
    __syncthreads();
    if (kz == 1) {
        #pragma unroll
        for (int a = 0; a < 16; a++) sred[grp][lane][a] = acc[a];
    }
    __syncthreads();
    if (kz == 0) {
        #pragma unroll
        for (int a = 0; a < 16; a++) acc[a] = add2(acc[a], sred[grp][lane][a]);

        #pragma unroll
        for (int jj = 0; jj < 2; jj++) {
            int j = jbase + jj;
            float gv0[4], gv1[4];
            #pragma unroll
            for (int g = 0; g < 4; g++) {
                float bs = bih[g * H_ + j] + bhh[g * H_ + j];
                int r = g * 2 + jj;
                gv0[g] = hsum2(acc[r*2+0]) + bs;
                gv1[g] = hsum2(acc[r*2+1]) + bs;
            }
            float2 cold = *(float2*)&cst[j * B_ + b2];
            float i0 = sigmf(gv0[0]), f0 = sigmf(gv0[1]), g0 = tanhf(gv0[2]), o0 = sigmf(gv0[3]);
            float i1 = sigmf(gv1[0]), f1 = sigmf(gv1[1]), g1 = tanhf(gv1[2]), o1 = sigmf(gv1[3]);
            float c0n = f0 * cold.x + i0 * g0;
            float c1n = f1 * cold.y + i1 * g1;
            *(float2*)&cst[j * B_ + b2] = make_float2(c0n, c1n);
            *(float2*)&hwr[j * B_ + b2] = make_float2(o0 * tanhf(c0n), o1 * tanhf(c1n));
        }
    }
}

// ================= logits + partial argmax =================
// grid 125, block 512 = 16 warps: bg = wid&1, rw = (wid>>1)&3 (10 cols each), kz = wid>>3.
// Warp tile: 10 vocab rows x 64 batch; lane owns 2 b. K-paired accumulators, no dup MOVs.
__global__ void __launch_bounds__(512) k_logits(
    const float* __restrict__ Wout, const float* __restrict__ bout,
    float* __restrict__ out, int t, int T)
{
    __shared__ __align__(16) u64 sredL[8][32][20];   // 40KB
    __shared__ float s_cv[4][B_];
    __shared__ int   s_ci[4][B_];

    const int tid = threadIdx.x, bid = blockIdx.x;
    const int lane = tid & 31, wid = tid >> 5;
    const int bg = wid & 1, rw = (wid >> 1) & 3, kz = wid >> 3;
    const int grp = wid & 7;                  // rw*2+bg
    const int b2 = bg * 64 + lane * 2;
    const int cbase = bid * 40 + rw * 10;

    const float* h1 = g_h1T[(t + 1) & 1];

    u64 acc[20];
    #pragma unroll
    for (int a = 0; a < 20; a++) acc[a] = 0ull;

    {
        const int k0 = kz * 256;
        #pragma unroll 4
        for (int k = k0; k < k0 + 256; k += 4) {
            const float* nb = h1 + (size_t)k * B_ + b2;
            float2 a0 = *(const float2*)(nb);
            float2 a1 = *(const float2*)(nb + B_);
            float2 a2 = *(const float2*)(nb + 2 * B_);
            float2 a3 = *(const float2*)(nb + 3 * B_);
            u64 xa0 = pack2(a0.x, a1.x), xa1 = pack2(a2.x, a3.x);
            u64 xb0 = pack2(a0.y, a1.y), xb1 = pack2(a2.y, a3.y);
            #pragma unroll
            for (int q = 0; q < 10; q++) {
                ulonglong2 w = *(const ulonglong2*)(Wout + (size_t)(cbase + q) * H_ + k);
                fma2(acc[q*2+0], xa0, w.x); fma2(acc[q*2+0], xa1, w.y);
                fma2(acc[q*2+1], xb0, w.x); fma2(acc[q*2+1], xb1, w.y);
            }
        }
    }

    // ---- cross-kz reduction: 2 -> 1 ----
    if (kz == 1) {
        #pragma unroll
        for (int a = 0; a < 20; a++) sredL[grp][lane][a] = acc[a];
    }
    __syncthreads();
    if (kz == 0) {
        #pragma unroll
        for (int a = 0; a < 20; a++) acc[a] = add2(acc[a], sredL[grp][lane][a]);

        // ---- epilogue: bias, write, per-lane argmax over 10 rows x 2 b ----
        float* op0 = out + ((size_t)(b2 + 0) * T + t) * V_ + cbase;
        float* op1 = out + ((size_t)(b2 + 1) * T + t) * V_ + cbase;
        float bv0 = -FLT_MAX, bv1 = -FLT_MAX; int bi0 = 0, bi1 = 0;
        #pragma unroll
        for (int q = 0; q < 10; q++) {
            float bq = bout[cbase + q];
            float v0 = hsum2(acc[q*2+0]) + bq;
            float v1 = hsum2(acc[q*2+1]) + bq;
            op0[q] = v0;
            op1[q] = v1;
            int col = cbase + q;
            if (v0 > bv0) { bv0 = v0; bi0 = col; }   // first max on ties
            if (v1 > bv1) { bv1 = v1; bi1 = col; }
        }
        s_cv[rw][b2]     = bv0;  s_ci[rw][b2]     = bi0;
        s_cv[rw][b2 + 1] = bv1;  s_ci[rw][b2 + 1] = bi1;
    }
    __syncthreads();
    if (tid < B_) {
        int b = tid;
        float bv = -FLT_MAX; int bi = 0x7fffffff;
        #pragma unroll
        for (int p = 0; p < 4; p++) {
            float v = s_cv[p][b]; int ix = s_ci[p][b];
            if (v > bv || (v == bv && ix < bi)) { bv = v; bi = ix; }
        }
        g_cval[bid * B_ + b] = bv;
        g_cidx[bid * B_ + b] = bi;
    }
}

// ================= final heads =================
__global__ void k_head(const float* __restrict__ Watt, const float* __restrict__ batt,
                       const float* __restrict__ Wsoph, const float* __restrict__ bsoph,
                       float* __restrict__ out, int T)
{
    const float* h1 = g_h1T[T & 1];
    int m = blockIdx.x;          // 0..23
    int b = threadIdx.x;         // 0..127
    size_t base = (size_t)B_ * T * V_;
    const float* w; float bias; float* op;
    if (m < 8) {
        w = Watt + m * H_; bias = batt[m];
        op = out + base + (size_t)b * 8 + m;
    } else {
        int mm = m - 8;
        w = Wsoph + mm * H_; bias = bsoph[mm];
        op = out + base + (size_t)B_ * 8 + (size_t)b * 16 + mm;
    }
    float a = 0.f;
    #pragma unroll 4
    for (int k = 0; k < H_; k += 4) {
        float4 wv = *(const float4*)(w + k);
        a += h1[(k + 0) * B_ + b] * wv.x + h1[(k + 1) * B_ + b] * wv.y
           + h1[(k + 2) * B_ + b] * wv.z + h1[(k + 3) * B_ + b] * wv.w;
    }
    *op = a + bias;
}

// ================= launch =================
extern "C" void kernel_launch(void* const* d_in, const int* in_sizes, int n_in,
                              void* d_out, int out_size)
{
    const float* noise = (const float*)d_in[0];
    const float* emb   = (const float*)d_in[1];
    const float* Wih0  = (const float*)d_in[2];
    const float* Whh0  = (const float*)d_in[3];
    const float* bih0  = (const float*)d_in[4];
    const float* bhh0  = (const float*)d_in[5];
    const float* Wih1  = (const float*)d_in[6];
    const float* Whh1  = (const float*)d_in[7];
    const float* bih1  = (const float*)d_in[8];
    const float* bhh1  = (const float*)d_in[9];
    const float* Wout  = (const float*)d_in[10];
    const float* bout  = (const float*)d_in[11];
    const float* Watt  = (const float*)d_in[12];
    const float* batt  = (const float*)d_in[13];
    const float* Wsoph = (const float*)d_in[14];
    const float* bsoph = (const float*)d_in[15];
    float* out = (float*)d_out;

    int T = (out_size - B_ * 24) / (B_ * V_);
    if (T <= 0) T = 200;

    k_init<<<256, 256>>>(noise);
    for (int t = 0; t < T; t++) {
        k_lstm<0><<<128, 512>>>(emb, Wih0, Whh0, bih0, bhh0, t);
        k_lstm<1><<<128, 512>>>(emb, Wih1, Whh1, bih1, bhh1, t);
        k_logits<<<125, 512>>>(Wout, bout, out, t, T);
    }
    k_head<<<24, 128>>>(Watt, batt, Wsoph, bsoph, out, T);
}

// round 16
// speedup vs baseline: 1.3236x; 1.3236x over previous
#include <cuda_runtime.h>
#include <math.h>
#include <float.h>

#define B_   128
#define H_   512
#define E_   256
#define ND_  128
#define V_   5000
#define K0_  384      // E_ + ND_

typedef unsigned long long u64;

// ---------------- persistent device state ----------------
__device__ __align__(16) float g_h0T[2][H_ * B_];   // [k][b], ping-pong
__device__ __align__(16) float g_h1T[2][H_ * B_];
__device__ __align__(16) float g_c0[H_ * B_];       // cell state [j][b]
__device__ __align__(16) float g_c1[H_ * B_];
__device__ __align__(16) float g_x0[K0_ * B_];      // [k][b]: emb per step, noise static
__device__ __align__(16) float g_cval[128 * B_];    // [p][b]
__device__ int   g_cidx[128 * B_];

__device__ __forceinline__ float sigmf(float x) { return 1.0f / (1.0f + expf(-x)); }

__device__ __forceinline__ u64 dup2(float a) {
    u64 r; asm("mov.b64 %0,{%1,%1};" : "=l"(r) : "f"(a)); return r;
}
__device__ __forceinline__ void fma2(u64& d, u64 x, u64 w) {
    asm("fma.rn.f32x2 %0,%1,%2,%0;" : "+l"(d) : "l"(x), "l"(w));
}
__device__ __forceinline__ u64 add2(u64 a, u64 b) {
    u64 r; asm("add.rn.f32x2 %0,%1,%2;" : "=l"(r) : "l"(a), "l"(b)); return r;
}
__device__ __forceinline__ void unpack2(u64 a, float& x, float& y) {
    asm("mov.b64 {%0,%1},%2;" : "=f"(x), "=f"(y) : "l"(a));
}
// L1 prefetch one 128B line ahead (weights; imm offset reuses load address reg)
#define PFW(P) asm volatile("prefetch.global.L1 [%0+128];" :: "l"((const float*)(P)))
// L1 prefetch 32 k-rows ahead in [k][B_] layout (32*128*4 = 16384 bytes)
#define PFX(P) asm volatile("prefetch.global.L1 [%0+16384];" :: "l"((const float*)(P)))

// 8-row GEMM slab body: rows' weight ptrs W0..W7 (warp-uniform), x in [k][B_] layout.
// acc[16] = [row r][batch-pair p]; lane4 = lane*4.
#define ROWF(WP, AI) do {                                              \
    const float* wp_ = (WP) + k;                                       \
    float4 wv_ = *(const float4*)wp_;                                  \
    PFW(wp_);                                                          \
    u64 wa_ = dup2(wv_.x), wb_ = dup2(wv_.y),                          \
        wc_ = dup2(wv_.z), wd_ = dup2(wv_.w);                          \
    fma2(acc[(AI)*2+0], xq0.x, wa_); fma2(acc[(AI)*2+1], xq0.y, wa_);  \
    fma2(acc[(AI)*2+0], xq1.x, wb_); fma2(acc[(AI)*2+1], xq1.y, wb_);  \
    fma2(acc[(AI)*2+0], xq2.x, wc_); fma2(acc[(AI)*2+1], xq2.y, wc_);  \
    fma2(acc[(AI)*2+0], xq3.x, wd_); fma2(acc[(AI)*2+1], xq3.y, wd_);  \
} while (0)

#define SEG8(XB, W0,W1,W2,W3,W4,W5,W6,W7, KLO, KLEN) do {              \
    const float* xb_ = (XB);                                           \
    _Pragma("unroll 2")                                                \
    for (int k = (KLO); k < (KLO) + (KLEN); k += 4) {                  \
        const float* xp0_ = xb_ + (size_t)(k+0)*B_ + lane4;            \
        const float* xp1_ = xb_ + (size_t)(k+1)*B_ + lane4;            \
        const float* xp2_ = xb_ + (size_t)(k+2)*B_ + lane4;            \
        const float* xp3_ = xb_ + (size_t)(k+3)*B_ + lane4;            \
        ulonglong2 xq0 = *(const ulonglong2*)xp0_;                     \
        ulonglong2 xq1 = *(const ulonglong2*)xp1_;                     \
        ulonglong2 xq2 = *(const ulonglong2*)xp2_;                     \
        ulonglong2 xq3 = *(const ulonglong2*)xp3_;                     \
        PFX(xp0_); PFX(xp1_); PFX(xp2_); PFX(xp3_);                    \
        ROWF(W0,0); ROWF(W1,1); ROWF(W2,2); ROWF(W3,3);                \
        ROWF(W4,4); ROWF(W5,5); ROWF(W6,6); ROWF(W7,7);                \
    }                                                                  \
} while (0)

// ================= init: zero state, transpose noise =================
__global__ void k_init(const float* __restrict__ noise) {
    int i = blockIdx.x * 256 + threadIdx.x;
    if (i < H_ * B_) {
        g_h0T[0][i] = 0.f; g_h1T[0][i] = 0.f;
        g_c0[i] = 0.f;     g_c1[i] = 0.f;
    }
    if (i < ND_ * B_) {
        int k = i >> 7, b = i & 127;
        g_x0[(E_ + k) * B_ + b] = noise[b * ND_ + k];
    }
}

// ================= token reduce + embedding gather/transpose =================
__global__ void k_gather(const float* __restrict__ emb, int t) {
    int b = threadIdx.x;
    int tok = 1;
    if (t > 0) {
        float bv = -FLT_MAX; int bi = 0x7fffffff;
        for (int p = 0; p < 125; p++) {
            float v = g_cval[p * B_ + b]; int ix = g_cidx[p * B_ + b];
            if (v > bv || (v == bv && ix < bi)) { bv = v; bi = ix; }
        }
        tok = bi;
    }
    int k0 = blockIdx.x * 4;
    float4 e = *(const float4*)(emb + (size_t)tok * E_ + k0);
    g_x0[(k0 + 0) * B_ + b] = e.x;
    g_x0[(k0 + 1) * B_ + b] = e.y;
    g_x0[(k0 + 2) * B_ + b] = e.z;
    g_x0[(k0 + 3) * B_ + b] = e.w;
}

// ================= LSTM layers =================
// grid 128, block 256 = 8 warps = 4 kz x 2 rw. Warp rows = 4 gates x 2 j.
__device__ __forceinline__ void lstm_epilogue(
    u64 acc[16], const float* __restrict__ bih, const float* __restrict__ bhh,
    float* __restrict__ cst, float* __restrict__ hwr, int jbase, int lane4)
{
    #pragma unroll
    for (int jj = 0; jj < 2; jj++) {
        int j = jbase + jj;
        float gv[4][4];
        #pragma unroll
        for (int g = 0; g < 4; g++) {
            unpack2(acc[(g*2+jj)*2 + 0], gv[g][0], gv[g][1]);
            unpack2(acc[(g*2+jj)*2 + 1], gv[g][2], gv[g][3]);
        }
        float bsum[4];
        #pragma unroll
        for (int g = 0; g < 4; g++) bsum[g] = bih[g * H_ + j] + bhh[g * H_ + j];
        float4 c4 = *(float4*)&cst[j * B_ + lane4];
        float cc[4] = {c4.x, c4.y, c4.z, c4.w};
        float hh[4];
        #pragma unroll
        for (int i = 0; i < 4; i++) {
            float iv = sigmf(gv[0][i] + bsum[0]);
            float fv = sigmf(gv[1][i] + bsum[1]);
            float gg = tanhf(gv[2][i] + bsum[2]);
            float ov = sigmf(gv[3][i] + bsum[3]);
            float cn = fv * cc[i] + iv * gg;
            cc[i] = cn;
            hh[i] = ov * tanhf(cn);
        }
        *(float4*)&cst[j * B_ + lane4] = make_float4(cc[0], cc[1], cc[2], cc[3]);
        *(float4*)&hwr[j * B_ + lane4] = make_float4(hh[0], hh[1], hh[2], hh[3]);
    }
}

__global__ void __launch_bounds__(256, 1) k_lstm0(
    const float* __restrict__ noise, const float* __restrict__ emb,
    const float* __restrict__ Wih, const float* __restrict__ Whh,
    const float* __restrict__ bih, const float* __restrict__ bhh, int t)
{
    __shared__ u64 sred[6][32][16];
    const int tid = threadIdx.x, lane = tid & 31, wid = tid >> 5;
    const int kz = wid >> 1, rw = wid & 1;
    const int lane4 = lane * 4;
    const int jbase = blockIdx.x * 4 + rw * 2;

    const float* h0rd = g_h0T[t & 1];
    float*       h0wr = g_h0T[(t + 1) & 1];

    u64 acc[16];
    #pragma unroll
    for (int a = 0; a < 16; a++) acc[a] = 0ull;

    {
        const float* w0 = Wih + (size_t)(0*H_ + jbase + 0) * K0_;
        const float* w1 = Wih + (size_t)(0*H_ + jbase + 1) * K0_;
        const float* w2 = Wih + (size_t)(1*H_ + jbase + 0) * K0_;
        const float* w3 = Wih + (size_t)(1*H_ + jbase + 1) * K0_;
        const float* w4 = Wih + (size_t)(2*H_ + jbase + 0) * K0_;
        const float* w5 = Wih + (size_t)(2*H_ + jbase + 1) * K0_;
        const float* w6 = Wih + (size_t)(3*H_ + jbase + 0) * K0_;
        const float* w7 = Wih + (size_t)(3*H_ + jbase + 1) * K0_;
        SEG8(g_x0, w0,w1,w2,w3,w4,w5,w6,w7, kz * 96, 96);
    }
    {
        const float* w0 = Whh + (size_t)(0*H_ + jbase + 0) * H_;
        const float* w1 = Whh + (size_t)(0*H_ + jbase + 1) * H_;
        const float* w2 = Whh + (size_t)(1*H_ + jbase + 0) * H_;
        const float* w3 = Whh + (size_t)(1*H_ + jbase + 1) * H_;
        const float* w4 = Whh + (size_t)(2*H_ + jbase + 0) * H_;
        const float* w5 = Whh + (size_t)(2*H_ + jbase + 1) * H_;
        const float* w6 = Whh + (size_t)(3*H_ + jbase + 0) * H_;
        const float* w7 = Whh + (size_t)(3*H_ + jbase + 1) * H_;
        SEG8(h0rd, w0,w1,w2,w3,w4,w5,w6,w7, kz * 128, 128);
    }

    if (kz > 0) {
        #pragma unroll
        for (int a = 0; a < 16; a++) sred[(kz - 1) * 2 + rw][lane][a] = acc[a];
    }
    __syncthreads();
    if (kz == 0) {
        #pragma unroll
        for (int s = 0; s < 3; s++)
            #pragma unroll
            for (int a = 0; a < 16; a++)
                acc[a] = add2(acc[a], sred[s * 2 + rw][lane][a]);
        lstm_epilogue(acc, bih, bhh, g_c0, h0wr, jbase, lane4);
    }
}

__global__ void __launch_bounds__(256, 1) k_lstm1(
    const float* __restrict__ Wih, const float* __restrict__ Whh,
    const float* __restrict__ bih, const float* __restrict__ bhh, int t)
{
    __shared__ u64 sred[6][32][16];
    const int tid = threadIdx.x, lane = tid & 31, wid = tid >> 5;
    const int kz = wid >> 1, rw = wid & 1;
    const int lane4 = lane * 4;
    const int jbase = blockIdx.x * 4 + rw * 2;

    const float* h0n  = g_h0T[(t + 1) & 1];
    const float* h1rd = g_h1T[t & 1];
    float*       h1wr = g_h1T[(t + 1) & 1];

    u64 acc[16];
    #pragma unroll
    for (int a = 0; a < 16; a++) acc[a] = 0ull;

    {
        const float* w0 = Wih + (size_t)(0*H_ + jbase + 0) * H_;
        const float* w1 = Wih + (size_t)(0*H_ + jbase + 1) * H_;
        const float* w2 = Wih + (size_t)(1*H_ + jbase + 0) * H_;
        const float* w3 = Wih + (size_t)(1*H_ + jbase + 1) * H_;
        const float* w4 = Wih + (size_t)(2*H_ + jbase + 0) * H_;
        const float* w5 = Wih + (size_t)(2*H_ + jbase + 1) * H_;
        const float* w6 = Wih + (size_t)(3*H_ + jbase + 0) * H_;
        const float* w7 = Wih + (size_t)(3*H_ + jbase + 1) * H_;
        SEG8(h0n, w0,w1,w2,w3,w4,w5,w6,w7, kz * 128, 128);
    }
    {
        const float* w0 = Whh + (size_t)(0*H_ + jbase + 0) * H_;
        const float* w1 = Whh + (size_t)(0*H_ + jbase + 1) * H_;
        const float* w2 = Whh + (size_t)(1*H_ + jbase + 0) * H_;
        const float* w3 = Whh + (size_t)(1*H_ + jbase + 1) * H_;
        const float* w4 = Whh + (size_t)(2*H_ + jbase + 0) * H_;
        const float* w5 = Whh + (size_t)(2*H_ + jbase + 1) * H_;
        const float* w6 = Whh + (size_t)(3*H_ + jbase + 0) * H_;
        const float* w7 = Whh + (size_t)(3*H_ + jbase + 1) * H_;
        SEG8(h1rd, w0,w1,w2,w3,w4,w5,w6,w7, kz * 128, 128);
    }

    if (kz > 0) {
        #pragma unroll
        for (int a = 0; a < 16; a++) sred[(kz - 1) * 2 + rw][lane][a] = acc[a];
    }
    __syncthreads();
    if (kz == 0) {
        #pragma unroll
        for (int s = 0; s < 3; s++)
            #pragma unroll
            for (int a = 0; a < 16; a++)
                acc[a] = add2(acc[a], sred[s * 2 + rw][lane][a]);
        lstm_epilogue(acc, bih, bhh, g_c1, h1wr, jbase, lane4);
    }
}

// ================= logits + partial argmax =================
// grid 125, block 512 = 16 warps = 2 kz x 8 rw. Warp: 5 vocab rows x 128 batch.
__global__ void __launch_bounds__(512, 1) k_logits(
    const float* __restrict__ Wout, const float* __restrict__ bout,
    float* __restrict__ out, int t, int T)
{
    __shared__ u64   sred[8][32][10];
    __shared__ float s_cv[8][B_];
    __shared__ int   s_ci[8][B_];

    const int tid = threadIdx.x, lane = tid & 31, wid = tid >> 5;
    const int kz = wid >> 3, rw = wid & 7;
    const int lane4 = lane * 4;
    const int cbase = blockIdx.x * 40 + rw * 5;

    const float* h1 = g_h1T[(t + 1) & 1];
    const float* w0 = Wout + (size_t)(cbase + 0) * H_;
    const float* w1 = Wout + (size_t)(cbase + 1) * H_;
    const float* w2 = Wout + (size_t)(cbase + 2) * H_;
    const float* w3 = Wout + (size_t)(cbase + 3) * H_;
    const float* w4 = Wout + (size_t)(cbase + 4) * H_;

    u64 acc[10];
    #pragma unroll
    for (int a = 0; a < 10; a++) acc[a] = 0ull;

#define ROWF5(WP, AI) do {                                             \
    const float* wp_ = (WP) + k;                                       \
    float4 wv_ = *(const float4*)wp_;                                  \
    PFW(wp_);                                                          \
    u64 wa_ = dup2(wv_.x), wb_ = dup2(wv_.y),                          \
        wc_ = dup2(wv_.z), wd_ = dup2(wv_.w);                          \
    fma2(acc[(AI)*2+0], xq0.x, wa_); fma2(acc[(AI)*2+1], xq0.y, wa_);  \
    fma2(acc[(AI)*2+0], xq1.x, wb_); fma2(acc[(AI)*2+1], xq1.y, wb_);  \
    fma2(acc[(AI)*2+0], xq2.x, wc_); fma2(acc[(AI)*2+1], xq2.y, wc_);  \
    fma2(acc[(AI)*2+0], xq3.x, wd_); fma2(acc[(AI)*2+1], xq3.y, wd_);  \
} while (0)

    {
        #pragma unroll 2
        for (int k = kz * 256; k < kz * 256 + 256; k += 4) {
            const float* xp0_ = h1 + (size_t)(k+0)*B_ + lane4;
            const float* xp1_ = h1 + (size_t)(k+1)*B_ + lane4;
            const float* xp2_ = h1 + (size_t)(k+2)*B_ + lane4;
            const float* xp3_ = h1 + (size_t)(k+3)*B_ + lane4;
            ulonglong2 xq0 = *(const ulonglong2*)xp0_;
            ulonglong2 xq1 = *(const ulonglong2*)xp1_;
            ulonglong2 xq2 = *(const ulonglong2*)xp2_;
            ulonglong2 xq3 = *(const ulonglong2*)xp3_;
            PFX(xp0_); PFX(xp1_); PFX(xp2_); PFX(xp3_);
            ROWF5(w0,0); ROWF5(w1,1); ROWF5(w2,2); ROWF5(w3,3); ROWF5(w4,4);
        }
    }
#undef ROWF5

    if (kz == 1) {
        #pragma unroll
        for (int a = 0; a < 10; a++) sred[rw][lane][a] = acc[a];
    }
    __syncthreads();
    if (kz == 0) {
        #pragma unroll
        for (int a = 0; a < 10; a++) acc[a] = add2(acc[a], sred[rw][lane][a]);

        float vals[5][4];
        #pragma unroll
        for (int q = 0; q < 5; q++) {
            float bq = bout[cbase + q];
            float v0, v1, v2, v3;
            unpack2(acc[q*2+0], v0, v1);
            unpack2(acc[q*2+1], v2, v3);
            vals[q][0] = v0 + bq; vals[q][1] = v1 + bq;
            vals[q][2] = v2 + bq; vals[q][3] = v3 + bq;
        }
        #pragma unroll
        for (int i = 0; i < 4; i++) {
            int b = lane4 + i;
            float* op = out + ((size_t)b * T + t) * V_ + cbase;
            float bv = -FLT_MAX; int bix = 0;
            #pragma unroll
            for (int q = 0; q < 5; q++) {
                float v = vals[q][i];
                op[q] = v;
                if (v > bv) { bv = v; bix = cbase + q; }   // first max on ties
            }
            s_cv[rw][b] = bv;
            s_ci[rw][b] = bix;
        }
    }
    __syncthreads();
    if (tid < B_) {
        int b = tid;
        float bv = -FLT_MAX; int bi = 0x7fffffff;
        #pragma unroll
        for (int p = 0; p < 8; p++) {
            float v = s_cv[p][b]; int ix = s_ci[p][b];
            if (v > bv || (v == bv && ix < bi)) { bv = v; bi = ix; }
        }
        g_cval[blockIdx.x * B_ + b] = bv;   // [p][b] layout, matches k_gather
        g_cidx[blockIdx.x * B_ + b] = bi;
    }
}

// ================= final heads =================
__global__ void k_head(const float* __restrict__ Watt, const float* __restrict__ batt,
                       const float* __restrict__ Wsoph, const float* __restrict__ bsoph,
                       float* __restrict__ out, int T)
{
    const float* h1 = g_h1T[T & 1];
    int m = blockIdx.x;          // 0..23
    int b = threadIdx.x;         // 0..127
    size_t base = (size_t)B_ * T * V_;
    const float* w; float bias; float* op;
    if (m < 8) {
        w = Watt + m * H_; bias = batt[m];
        op = out + base + (size_t)b * 8 + m;
    } else {
        int mm = m - 8;
        w = Wsoph + mm * H_; bias = bsoph[mm];
        op = out + base + (size_t)B_ * 8 + (size_t)b * 16 + mm;
    }
    float a = 0.f;
    #pragma unroll 4
    for (int k = 0; k < H_; k += 4) {
        float4 wv = *(const float4*)(w + k);
        a += h1[(k + 0) * B_ + b] * wv.x + h1[(k + 1) * B_ + b] * wv.y
           + h1[(k + 2) * B_ + b] * wv.z + h1[(k + 3) * B_ + b] * wv.w;
    }
    *op = a + bias;
}

// ================= launch =================
extern "C" void kernel_launch(void* const* d_in, const int* in_sizes, int n_in,
                              void* d_out, int out_size)
{
    const float* noise = (const float*)d_in[0];
    const float* emb   = (const float*)d_in[1];
    const float* Wih0  = (const float*)d_in[2];
    const float* Whh0  = (const float*)d_in[3];
    const float* bih0  = (const float*)d_in[4];
    const float* bhh0  = (const float*)d_in[5];
    const float* Wih1  = (const float*)d_in[6];
    const float* Whh1  = (const float*)d_in[7];
    const float* bih1  = (const float*)d_in[8];
    const float* bhh1  = (const float*)d_in[9];
    const float* Wout  = (const float*)d_in[10];
    const float* bout  = (const float*)d_in[11];
    const float* Watt  = (const float*)d_in[12];
    const float* batt  = (const float*)d_in[13];
    const float* Wsoph = (const float*)d_in[14];
    const float* bsoph = (const float*)d_in[15];
    float* out = (float*)d_out;

    int T = (out_size - B_ * 24) / (B_ * V_);
    if (T <= 0) T = 200;

    k_init<<<256, 256>>>(noise);
    for (int t = 0; t < T; t++) {
        k_gather<<<64, 128>>>(emb, t);
        k_lstm0<<<128, 256>>>(noise, emb, Wih0, Whh0, bih0, bhh0, t);
        k_lstm1<<<128, 256>>>(Wih1, Whh1, bih1, bhh1, t);
        k_logits<<<125, 512>>>(Wout, bout, out, t, T);
    }
    k_head<<<24, 128>>>(Watt, batt, Wsoph, bsoph, out, T);
}